// round 2
// baseline (speedup 1.0000x reference)
#include <cuda_runtime.h>
#include <cstdint>
#include <math.h>

// Problem constants: x [256,4096] int32 in {0..5}
#define BB   256
#define SS   4096
#define VV   6
#define DD   32
#define HH   16
#define PADV 5
#define KK   614          // max(1, int(4096*0.15))
#define CL   4            // CTAs per row (cluster size)
#define TPB  256
#define TOKC (SS / CL)    // 1024 tokens per CTA
#define NW   (TPB / 32)   // 8 warps

__device__ __forceinline__ uint32_t smem_u32(const void* p) {
    uint32_t a;
    asm("{ .reg .u64 t; cvta.to.shared.u64 t, %1; cvt.u32.u64 %0, t; }"
        : "=r"(a) : "l"(p));
    return a;
}
__device__ __forceinline__ void st_dsmem_i32(uint32_t local_addr, uint32_t rank, int val) {
    uint32_t rem;
    asm volatile("mapa.shared::cluster.u32 %0, %1, %2;" : "=r"(rem) : "r"(local_addr), "r"(rank));
    asm volatile("st.shared::cluster.b32 [%0], %1;" :: "r"(rem), "r"(val) : "memory");
}

// One row of x handled by a 4-CTA cluster; each CTA owns 1024 contiguous tokens.
__global__ __launch_bounds__(TPB, 4) __cluster_dims__(CL, 1, 1)
void fused_row_kernel(
    const int*   __restrict__ x,
    const float* __restrict__ emb,
    const float* __restrict__ sw1, const float* __restrict__ sb1,
    const float* __restrict__ sw2, const float* __restrict__ sb2,
    const float* __restrict__ aw1, const float* __restrict__ ab1,
    const float* __restrict__ aw2, const float* __restrict__ ab2,
    const float* __restrict__ cw1, const float* __restrict__ cb1,
    const float* __restrict__ cw2, const float* __restrict__ cb2,
    float* __restrict__ out_pred,
    float* __restrict__ out_top,
    float* __restrict__ out_sc)
{
    __shared__ float table[VV][DD];
    __shared__ float rbuf[VV][DD];
    __shared__ float hbuf[VV][HH];
    __shared__ float arow[VV][DD];
    __shared__ float sscore[VV];
    __shared__ int   warpsum[NW][VV];   // per-warp totals -> exclusive prefixes
    __shared__ int   cta_counts[VV];    // this CTA's per-vocab totals
    __shared__ int   allc[CL][VV];      // gathered totals from all cluster CTAs
    __shared__ int   take[VV], obase[VV], cpre_sh[VV];
    __shared__ float pooled[DD];
    __shared__ float h2[HH];

    const int t    = threadIdx.x;
    const int lane = t & 31;
    const int warp = t >> 5;
    const int b    = blockIdx.x >> 2;   // row
    const int c    = blockIdx.x & 3;    // cluster rank / chunk

    // ---- issue x chunk load early: 4 contiguous tokens per thread ----
    const int4 xw = ((const int4*)(x + (size_t)b * SS + c * TOKC))[t];

    // table = emb with PAD row zeroed
    if (t < VV * DD) {
        int v = t >> 5, i = t & 31;
        table[v][i] = (v == PADV) ? 0.0f : emb[v * DD + i];
    }
    __syncthreads();                                           // S1

    // ---- tiny MLP hidden layers (per-vocab, redundant per CTA, L2-hot) ----
    if (t < VV * DD) {                   // approximator hidden
        int v = t >> 5, i = t & 31;
        float acc = ab1[i];
        #pragma unroll
        for (int d = 0; d < DD; ++d) acc += table[v][d] * aw1[d * DD + i];
        rbuf[v][i] = fmaxf(acc, 0.0f);
    }
    if (t < VV * HH) {                   // selector hidden
        int v = t >> 4, j = t & 15;
        float acc = sb1[j];
        #pragma unroll
        for (int d = 0; d < DD; ++d) acc += table[v][d] * sw1[d * HH + j];
        hbuf[v][j] = fmaxf(acc, 0.0f);
    }
    __syncthreads();                                           // S2

    // ---- output layers: arow + per-vocab sigmoid scores ----
    if (t < VV * DD) {
        int v = t >> 5, i = t & 31;
        float acc = ab2[i];
        #pragma unroll
        for (int m = 0; m < DD; ++m) acc += rbuf[v][m] * aw2[m * DD + i];
        arow[v][i] = acc;
    }
    if (t >= 224 && t < 224 + VV) {
        int v = t - 224;
        float acc = sb2[0];
        #pragma unroll
        for (int j = 0; j < HH; ++j) acc += hbuf[v][j] * sw2[j];
        sscore[v] = 1.0f / (1.0f + expf(-acc));
    }

    // ---- per-thread packed counts (6x10-bit) + warp inclusive scan ----
    unsigned long long cpack =
        (1ull << (10 * xw.x)) + (1ull << (10 * xw.y)) +
        (1ull << (10 * xw.z)) + (1ull << (10 * xw.w));
    const unsigned long long own = cpack;
    #pragma unroll
    for (int off = 1; off < 32; off <<= 1) {
        unsigned long long n = __shfl_up_sync(0xffffffffu, cpack, off);
        if (lane >= off) cpack += n;
    }
    if (lane == 31) {
        #pragma unroll
        for (int v = 0; v < VV; ++v)
            warpsum[warp][v] = (int)((cpack >> (10 * v)) & 1023ull);
    }
    __syncthreads();                                           // S3 (also publishes sscore/arow)

    // cross-warp exclusive scan -> CTA totals
    if (t < VV) {
        int run = 0;
        #pragma unroll
        for (int w = 0; w < NW; ++w) { int s = warpsum[w][t]; warpsum[w][t] = run; run += s; }
        cta_counts[t] = run;
    }
    __syncthreads();                                           // S4

    // ---- push this CTA's totals into every cluster peer's allc[c][*] ----
    if (t < CL * VV) {
        int r = t / VV, v = t % VV;
        st_dsmem_i32(smem_u32(&allc[c][v]), (uint32_t)r, cta_counts[v]);
    }
    asm volatile("barrier.cluster.arrive.aligned;" ::: "memory");

    // ---- scores output (overlapped with cluster barrier wait) ----
    {
        float4 f;
        f.x = sscore[xw.x]; f.y = sscore[xw.y];
        f.z = sscore[xw.z]; f.w = sscore[xw.w];
        ((float4*)(out_sc + (size_t)b * SS + c * TOKC))[t] = f;
    }
    asm volatile("barrier.cluster.wait.aligned;" ::: "memory");

    // ---- row-level totals, rank vocab by score, budget split ----
    if (t == 0) {
        int rowtot[VV];
        #pragma unroll
        for (int v = 0; v < VV; ++v) {
            int tot = 0, pre = 0;
            #pragma unroll
            for (int r = 0; r < CL; ++r) { int s = allc[r][v]; if (r < c) pre += s; tot += s; }
            rowtot[v] = tot; cpre_sh[v] = pre;
        }
        // stable selection sort of 6 scores, descending (ties: lower vocab first)
        int order[VV];
        #pragma unroll
        for (int v = 0; v < VV; ++v) order[v] = v;
        for (int a = 0; a < VV; ++a) {
            int best = a;
            for (int q = a + 1; q < VV; ++q)
                if (sscore[order[q]] > sscore[order[best]]) best = q;
            int tmp = order[a]; order[a] = order[best]; order[best] = tmp;
        }
        int budget = KK, off = 0;
        #pragma unroll
        for (int r = 0; r < VV; ++r) {
            int v  = order[r];
            int tk = min(rowtot[v], budget);
            take[v]  = tk;
            obase[v] = off;
            off    += tk;
            budget -= tk;
        }
    }
    __syncthreads();                                           // S5

    // ---- emit top_idx (stable: ascending position within vocab) ----
    {
        const unsigned long long excl = cpack - own;
        int o[VV];
        #pragma unroll
        for (int v = 0; v < VV; ++v)
            o[v] = cpre_sh[v] + warpsum[warp][v] + (int)((excl >> (10 * v)) & 1023ull);

        float* trow = out_top + (size_t)b * KK;
        const int pbase = c * TOKC + t * 4;
        const int tok[4] = {xw.x, xw.y, xw.z, xw.w};
        #pragma unroll
        for (int j = 0; j < 4; ++j) {
            int v   = tok[j];
            int ord = o[v]++;
            if (ord < take[v])
                trow[obase[v] + ord] = (float)(pbase + j);
        }
    }

    // ---- pooled mean + classifier (rank-0 CTA only) ----
    if (c == 0) {
        if (t < DD) {
            float acc = 0.0f;
            #pragma unroll
            for (int v = 0; v < VV; ++v) acc += (float)take[v] * arow[v][t];
            pooled[t] = acc * (1.0f / (float)KK);
        }
        __syncthreads();
        if (t < HH) {
            float acc = cb1[t];
            #pragma unroll
            for (int d = 0; d < DD; ++d) acc += pooled[d] * cw1[d * HH + t];
            h2[t] = fmaxf(acc, 0.0f);
        }
        __syncthreads();
        if (t == 0) {
            float acc = cb2[0];
            #pragma unroll
            for (int j = 0; j < HH; ++j) acc += h2[j] * cw2[j];
            out_pred[b] = 1.0f / (1.0f + expf(-acc));
        }
    }
}

extern "C" void kernel_launch(void* const* d_in, const int* in_sizes, int n_in,
                              void* d_out, int out_size) {
    const int*   x   = (const int*)  d_in[0];
    const float* emb = (const float*)d_in[1];
    const float* sw1 = (const float*)d_in[2];
    const float* sb1 = (const float*)d_in[3];
    const float* sw2 = (const float*)d_in[4];
    const float* sb2 = (const float*)d_in[5];
    const float* aw1 = (const float*)d_in[6];
    const float* ab1 = (const float*)d_in[7];
    const float* aw2 = (const float*)d_in[8];
    const float* ab2 = (const float*)d_in[9];
    const float* cw1 = (const float*)d_in[10];
    const float* cb1 = (const float*)d_in[11];
    const float* cw2 = (const float*)d_in[12];
    const float* cb2 = (const float*)d_in[13];

    float* out      = (float*)d_out;
    float* out_pred = out;
    float* out_top  = out + BB;
    float* out_sc   = out + BB + (size_t)BB * KK;

    fused_row_kernel<<<BB * CL, TPB>>>(x, emb, sw1, sb1, sw2, sb2,
                                       aw1, ab1, aw2, ab2,
                                       cw1, cb1, cw2, cb2,
                                       out_pred, out_top, out_sc);
}

// round 3
// speedup vs baseline: 1.3208x; 1.3208x over previous
#include <cuda_runtime.h>
#include <cstdint>
#include <math.h>

#define BB   256
#define SS   4096
#define VV   6
#define DD   32
#define HH   16
#define PADV 5
#define KK   614          // max(1, int(4096*0.15))
#define CL   4            // chunks (CTAs) per row
#define TPB  256
#define TOKC (SS / CL)    // 1024 tokens per CTA
#define NW   (TPB / 32)

// Cross-kernel scratch (static device globals: allowed)
__device__ int   g_counts[BB][CL][VV];
__device__ float g_sscore[VV];
__device__ float g_arow[VV][DD];
__device__ int   g_order[VV];

// ---------------- K1: per-chunk vocab counts + (one CTA) vocab-level MLPs ----------------
__global__ __launch_bounds__(TPB, 8) void count_kernel(
    const int*   __restrict__ x,
    const float* __restrict__ emb,
    const float* __restrict__ sw1, const float* __restrict__ sb1,
    const float* __restrict__ sw2, const float* __restrict__ sb2,
    const float* __restrict__ aw1, const float* __restrict__ ab1,
    const float* __restrict__ aw2, const float* __restrict__ ab2)
{
    const int t = threadIdx.x;

    if (blockIdx.x < BB * CL) {
        // ---- counting CTA: 1024 tokens, 4 per thread ----
        const int b = blockIdx.x >> 2;
        const int c = blockIdx.x & 3;
        const int4 xw = ((const int4*)(x + (size_t)b * SS + c * TOKC))[t];

        unsigned long long cpack =
            (1ull << (10 * xw.x)) + (1ull << (10 * xw.y)) +
            (1ull << (10 * xw.z)) + (1ull << (10 * xw.w));
        #pragma unroll
        for (int off = 16; off > 0; off >>= 1)
            cpack += __shfl_xor_sync(0xffffffffu, cpack, off);

        __shared__ unsigned long long wtot[NW];
        if ((t & 31) == 0) wtot[t >> 5] = cpack;
        __syncthreads();
        if (t < VV) {
            int s = 0;
            #pragma unroll
            for (int w = 0; w < NW; ++w) s += (int)((wtot[w] >> (10 * t)) & 1023ull);
            g_counts[b][c][t] = s;
        }
        return;
    }

    // ---- single MLP CTA: vocab-level tables (row-independent) ----
    __shared__ float table[VV][DD];
    __shared__ float rbuf[VV][DD];
    __shared__ float hbuf[VV][HH];
    __shared__ float ssc[VV];

    if (t < VV * DD) {
        int v = t >> 5, i = t & 31;
        table[v][i] = (v == PADV) ? 0.0f : emb[v * DD + i];
    }
    __syncthreads();
    if (t < VV * DD) {                   // approximator hidden
        int v = t >> 5, i = t & 31;
        float acc = ab1[i];
        #pragma unroll
        for (int d = 0; d < DD; ++d) acc += table[v][d] * aw1[d * DD + i];
        rbuf[v][i] = fmaxf(acc, 0.0f);
    }
    if (t < VV * HH) {                   // selector hidden
        int v = t >> 4, j = t & 15;
        float acc = sb1[j];
        #pragma unroll
        for (int d = 0; d < DD; ++d) acc += table[v][d] * sw1[d * HH + j];
        hbuf[v][j] = fmaxf(acc, 0.0f);
    }
    __syncthreads();
    if (t < VV * DD) {                   // approximator output rows
        int v = t >> 5, i = t & 31;
        float acc = ab2[i];
        #pragma unroll
        for (int m = 0; m < DD; ++m) acc += rbuf[v][m] * aw2[m * DD + i];
        g_arow[v][i] = acc;
    }
    if (t >= 224 && t < 224 + VV) {      // selector score (sigmoid)
        int v = t - 224;
        float acc = sb2[0];
        #pragma unroll
        for (int j = 0; j < HH; ++j) acc += hbuf[v][j] * sw2[j];
        float s = 1.0f / (1.0f + expf(-acc));
        ssc[v] = s;
        g_sscore[v] = s;
    }
    __syncthreads();
    if (t == 0) {                        // stable descending rank (ties: lower vocab)
        int order[VV];
        #pragma unroll
        for (int v = 0; v < VV; ++v) order[v] = v;
        for (int a = 0; a < VV; ++a) {
            int best = a;
            for (int q = a + 1; q < VV; ++q)
                if (ssc[order[q]] > ssc[order[best]]) best = q;
            int tmp = order[a]; order[a] = order[best]; order[best] = tmp;
        }
        #pragma unroll
        for (int a = 0; a < VV; ++a) g_order[a] = order[a];
    }
}

// ---------------- K2: scores + top_idx + pred ----------------
__global__ __launch_bounds__(TPB, 8) void emit_kernel(
    const int*   __restrict__ x,
    const float* __restrict__ cw1, const float* __restrict__ cb1,
    const float* __restrict__ cw2, const float* __restrict__ cb2,
    float* __restrict__ out_pred,
    float* __restrict__ out_top,
    float* __restrict__ out_sc)
{
    __shared__ float sscore[VV];
    __shared__ int   allc[CL][VV];
    __shared__ int   order_sh[VV];
    __shared__ int   warpsum[NW][VV];    // per-warp totals -> exclusive prefixes
    __shared__ int   take[VV], obase[VV], cpre_sh[VV];
    __shared__ float pooled[DD];
    __shared__ float h2[HH];

    const int t    = threadIdx.x;
    const int lane = t & 31;
    const int warp = t >> 5;
    const int b    = blockIdx.x >> 2;
    const int c    = blockIdx.x & 3;

    // x chunk (L2-hot after K1)
    const int4 xw = ((const int4*)(x + (size_t)b * SS + c * TOKC))[t];

    // stage shared tables
    if (t < VV)                sscore[t] = g_sscore[t];
    if (t >= 32 && t < 32+VV)  order_sh[t - 32] = g_order[t - 32];
    if (t >= 64 && t < 64 + CL * VV) {
        int i = t - 64;
        allc[i / VV][i % VV] = g_counts[b][i / VV][i % VV];
    }

    // packed counts + warp inclusive scan (stability: ascending position)
    unsigned long long cpack =
        (1ull << (10 * xw.x)) + (1ull << (10 * xw.y)) +
        (1ull << (10 * xw.z)) + (1ull << (10 * xw.w));
    const unsigned long long own = cpack;
    #pragma unroll
    for (int off = 1; off < 32; off <<= 1) {
        unsigned long long n = __shfl_up_sync(0xffffffffu, cpack, off);
        if (lane >= off) cpack += n;
    }
    if (lane == 31) {
        #pragma unroll
        for (int v = 0; v < VV; ++v)
            warpsum[warp][v] = (int)((cpack >> (10 * v)) & 1023ull);
    }
    __syncthreads();                                           // S1

    // cross-warp exclusive scan (CTA-local)
    if (t < VV) {
        int run = 0;
        #pragma unroll
        for (int w = 0; w < NW; ++w) { int s = warpsum[w][t]; warpsum[w][t] = run; run += s; }
        // chunk-prefix for this CTA
        int pre = 0;
        #pragma unroll
        for (int r = 0; r < CL; ++r) if (r < c) pre += allc[r][t];
        cpre_sh[t] = pre;
    }
    if (t == 32) {                       // budget split over ranked vocabs
        int budget = KK, off = 0;
        #pragma unroll
        for (int r = 0; r < VV; ++r) {
            int v = order_sh[r];
            int tot = allc[0][v] + allc[1][v] + allc[2][v] + allc[3][v];
            int tk  = min(tot, budget);
            take[v]  = tk;
            obase[v] = off;
            off    += tk;
            budget -= tk;
        }
    }
    // scores output (needs only sscore, valid after S1)
    {
        float4 f;
        f.x = sscore[xw.x]; f.y = sscore[xw.y];
        f.z = sscore[xw.z]; f.w = sscore[xw.w];
        ((float4*)(out_sc + (size_t)b * SS + c * TOKC))[t] = f;
    }
    __syncthreads();                                           // S2

    // emit top_idx (stable within vocab; vocab blocks in score order)
    {
        const unsigned long long excl = cpack - own;
        int o[VV];
        #pragma unroll
        for (int v = 0; v < VV; ++v)
            o[v] = cpre_sh[v] + warpsum[warp][v] + (int)((excl >> (10 * v)) & 1023ull);

        float* trow = out_top + (size_t)b * KK;
        const int pbase = c * TOKC + t * 4;
        const int tok[4] = {xw.x, xw.y, xw.z, xw.w};
        #pragma unroll
        for (int j = 0; j < 4; ++j) {
            int v   = tok[j];
            int ord = o[v]++;
            if (ord < take[v])
                trow[obase[v] + ord] = (float)(pbase + j);
        }
    }

    // classifier (rank-0 chunk only)
    if (c == 0) {
        if (t < DD) {
            float acc = 0.0f;
            #pragma unroll
            for (int v = 0; v < VV; ++v) acc += (float)take[v] * g_arow[v][t];
            pooled[t] = acc * (1.0f / (float)KK);
        }
        __syncthreads();
        if (t < HH) {
            float acc = cb1[t];
            #pragma unroll
            for (int d = 0; d < DD; ++d) acc += pooled[d] * cw1[d * HH + t];
            h2[t] = fmaxf(acc, 0.0f);
        }
        __syncthreads();
        if (t == 0) {
            float acc = cb2[0];
            #pragma unroll
            for (int j = 0; j < HH; ++j) acc += h2[j] * cw2[j];
            out_pred[b] = 1.0f / (1.0f + expf(-acc));
        }
    }
}

extern "C" void kernel_launch(void* const* d_in, const int* in_sizes, int n_in,
                              void* d_out, int out_size) {
    const int*   x   = (const int*)  d_in[0];
    const float* emb = (const float*)d_in[1];
    const float* sw1 = (const float*)d_in[2];
    const float* sb1 = (const float*)d_in[3];
    const float* sw2 = (const float*)d_in[4];
    const float* sb2 = (const float*)d_in[5];
    const float* aw1 = (const float*)d_in[6];
    const float* ab1 = (const float*)d_in[7];
    const float* aw2 = (const float*)d_in[8];
    const float* ab2 = (const float*)d_in[9];
    const float* cw1 = (const float*)d_in[10];
    const float* cb1 = (const float*)d_in[11];
    const float* cw2 = (const float*)d_in[12];
    const float* cb2 = (const float*)d_in[13];

    float* out      = (float*)d_out;
    float* out_pred = out;
    float* out_top  = out + BB;
    float* out_sc   = out + BB + (size_t)BB * KK;

    count_kernel<<<BB * CL + 1, TPB>>>(x, emb, sw1, sb1, sw2, sb2,
                                       aw1, ab1, aw2, ab2);
    emit_kernel<<<BB * CL, TPB>>>(x, cw1, cb1, cw2, cb2,
                                  out_pred, out_top, out_sc);
}